// round 2
// baseline (speedup 1.0000x reference)
#include <cuda_runtime.h>
#include <math_constants.h>
#include <cstdint>

// ---------------- problem constants ----------------
#define NN      20000       // nodes
#define EE      320000      // edges
#define TT      12          // timesteps
#define IN_DIM  128
#define HID     256
#define OUTD    128
#define HEADS   4
#define NEG     0.2f

// ---------------- device scratch (no allocations allowed) ----------------
__device__ float g_hw  [(size_t)NN * HID];   // h = x @ W     (per layer)
__device__ float g_x   [(size_t)NN * HID];   // layer input / relu output
__device__ float g_agg [(size_t)NN * HID];   // segment-sum accumulator
__device__ float g_as  [NN * HEADS];
__device__ float g_ad  [NN * HEADS];
__device__ float g_emax[NN * HEADS];
__device__ float g_den [NN * HEADS];
__device__ float g_e   [(size_t)EE * HEADS]; // per-edge e, then w
__device__ int   g_src [EE];
__device__ int   g_dst [EE];
__device__ int   g_is64;

// ---------------- edge-index dtype detection + normalization ----------------
// The reference declares int64 edge_index, but JAX without x64 silently makes
// int32. Detect on-device: int64 view of int32-packed data is almost surely
// out of [0, NN) (high word = another random index).
__global__ void detect_k(const void* ei) {
    __shared__ int bad;
    if (threadIdx.x == 0) bad = 0;
    __syncthreads();
    const long long* p = (const long long*)ei;
    // 2048 int64 reads = 16KB, safe under either dtype (buffer >= 2.56MB)
    for (int i = threadIdx.x; i < 2048; i += blockDim.x) {
        long long v = p[i];
        if (v < 0 || v >= NN) bad = 1;
    }
    __syncthreads();
    if (threadIdx.x == 0) g_is64 = bad ? 0 : 1;
}

__global__ void convert_k(const void* ei) {
    int i = blockIdx.x * blockDim.x + threadIdx.x;
    if (i >= EE) return;
    if (g_is64) {
        const long long* p = (const long long*)ei;
        g_src[i] = (int)p[i];
        g_dst[i] = (int)p[EE + i];
    } else {
        const int* p = (const int*)ei;
        g_src[i] = p[i];
        g_dst[i] = p[EE + i];
    }
}

// ---------------- helpers ----------------
__device__ __forceinline__ void atomicMaxF(float* addr, float v) {
    if (v >= 0.0f) atomicMax((int*)addr, __float_as_int(v));
    else           atomicMin((unsigned int*)addr, __float_as_uint(v));
}

// ---------------- GEMM: C[N,M] = A[N,K](lda) * B[K,M] ----------------
// BM=128, BN=64, BK=16, 256 threads, thread tile 8x4
__global__ void gemm_k(const float* __restrict__ A, int lda,
                       const float* __restrict__ B,
                       float* __restrict__ C,
                       int Nrows, int K, int M) {
    __shared__ float As[16][128];
    __shared__ float Bs[16][64];
    const int tid = threadIdx.x;
    const int rm = blockIdx.y * 128;
    const int cn = blockIdx.x * 64;
    const int ty = tid >> 4;       // 0..15
    const int tx = tid & 15;       // 0..15

    float acc[8][4];
#pragma unroll
    for (int i = 0; i < 8; i++)
#pragma unroll
        for (int j = 0; j < 4; j++) acc[i][j] = 0.0f;

    for (int k0 = 0; k0 < K; k0 += 16) {
        // load A tile: 128 rows x 16 cols = 512 float4, 2 per thread
#pragma unroll
        for (int l = 0; l < 2; l++) {
            int idx = tid + l * 256;        // 0..511
            int r = idx >> 2;               // row in tile
            int q = idx & 3;                // float4 in row
            float4 v = make_float4(0.f, 0.f, 0.f, 0.f);
            int grow = rm + r;
            if (grow < Nrows)
                v = *(const float4*)(A + (size_t)grow * lda + k0 + q * 4);
            As[q * 4 + 0][r] = v.x;
            As[q * 4 + 1][r] = v.y;
            As[q * 4 + 2][r] = v.z;
            As[q * 4 + 3][r] = v.w;
        }
        // load B tile: 16 rows x 64 cols = 256 float4, 1 per thread
        {
            int kr = tid >> 4;
            int c4 = tid & 15;
            float4 v = *(const float4*)(B + (size_t)(k0 + kr) * M + cn + c4 * 4);
            *(float4*)&Bs[kr][c4 * 4] = v;
        }
        __syncthreads();
#pragma unroll
        for (int k = 0; k < 16; k++) {
            float a[8], b[4];
#pragma unroll
            for (int i = 0; i < 8; i++) a[i] = As[k][ty * 8 + i];
#pragma unroll
            for (int j = 0; j < 4; j++) b[j] = Bs[k][tx * 4 + j];
#pragma unroll
            for (int i = 0; i < 8; i++)
#pragma unroll
                for (int j = 0; j < 4; j++) acc[i][j] += a[i] * b[j];
        }
        __syncthreads();
    }
#pragma unroll
    for (int i = 0; i < 8; i++) {
        int grow = rm + ty * 8 + i;
        if (grow < Nrows) {
            float4 v = make_float4(acc[i][0], acc[i][1], acc[i][2], acc[i][3]);
            *(float4*)(C + (size_t)grow * M + cn + tx * 4) = v;
        }
    }
}

// ---------------- per-node attention logits + init ----------------
__global__ void node_prep_k(const float* __restrict__ hw,
                            const float* __restrict__ a_src,
                            const float* __restrict__ a_dst,
                            float* __restrict__ as_, float* __restrict__ ad_,
                            float* __restrict__ emax, float* __restrict__ den,
                            int N, int C) {
    int idx = blockIdx.x * blockDim.x + threadIdx.x;  // n*HEADS + h
    if (idx >= N * HEADS) return;
    int n = idx >> 2;
    int h = idx & 3;
    const float* hp = hw + (size_t)n * (HEADS * C) + h * C;
    const float* s = a_src + h * C;
    const float* d = a_dst + h * C;
    float va = 0.f, vd = 0.f;
    for (int c = 0; c < C; c++) {
        float x = hp[c];
        va += x * s[c];
        vd += x * d[c];
    }
    as_[idx] = va;
    ad_[idx] = vd;
    emax[idx] = -CUDART_INF_F;
    den[idx] = 0.f;
}

// ---------------- edge pass 1: leaky-relu logit + segment max ----------------
__global__ void edge_max_k(const int* __restrict__ src,
                           const int* __restrict__ dst,
                           const float* __restrict__ as_,
                           const float* __restrict__ ad_,
                           float* __restrict__ ee, float* __restrict__ emax,
                           int E) {
    int e = blockIdx.x * blockDim.x + threadIdx.x;
    if (e >= E) return;
    int s = src[e];
    int d = dst[e];
#pragma unroll
    for (int h = 0; h < HEADS; h++) {
        float v = as_[s * HEADS + h] + ad_[d * HEADS + h];
        v = (v > 0.f) ? v : NEG * v;
        ee[(size_t)e * HEADS + h] = v;
        atomicMaxF(&emax[d * HEADS + h], v);
    }
}

// ---------------- edge pass 2: exp + segment sum ----------------
__global__ void edge_exp_k(const int* __restrict__ dst,
                           float* __restrict__ ee,
                           const float* __restrict__ emax,
                           float* __restrict__ den, int E) {
    int e = blockIdx.x * blockDim.x + threadIdx.x;
    if (e >= E) return;
    int d = dst[e];
#pragma unroll
    for (int h = 0; h < HEADS; h++) {
        float w = expf(ee[(size_t)e * HEADS + h] - emax[d * HEADS + h]);
        ee[(size_t)e * HEADS + h] = w;
        atomicAdd(&den[d * HEADS + h], w);
    }
}

// ---------------- edge pass 3: weighted message aggregation ----------------
// one warp per edge; lane strides over M columns
__global__ void edge_agg_k(const int* __restrict__ src,
                           const int* __restrict__ dst,
                           const float* __restrict__ w,
                           const float* __restrict__ den,
                           const float* __restrict__ hw,
                           float* __restrict__ agg,
                           int E, int M, int logC) {
    int warp = (blockIdx.x * blockDim.x + threadIdx.x) >> 5;
    int lane = threadIdx.x & 31;
    if (warp >= E) return;
    int s = src[warp];
    int d = dst[warp];
    float aval = 0.f;
    if (lane < HEADS)
        aval = w[(size_t)warp * HEADS + lane] / (den[d * HEADS + lane] + 1e-16f);
    const float* hp = hw + (size_t)s * M;
    float* op = agg + (size_t)d * M;
    for (int col = lane; col < M; col += 32) {
        int h = col >> logC;
        float alpha = __shfl_sync(0xffffffff, aval, h);
        atomicAdd(op + col, hp[col] * alpha);
    }
}

// ---------------- finalize: + bias (+ relu), strided store ----------------
__global__ void finalize_k(const float* __restrict__ agg,
                           const float* __restrict__ bias,
                           float* __restrict__ out,
                           int N, int M, int ostride, int dorelu) {
    int idx = blockIdx.x * blockDim.x + threadIdx.x;
    if (idx >= N * M) return;
    int n = idx / M;
    int c = idx - n * M;
    float v = agg[idx] + bias[c];
    if (dorelu) v = fmaxf(v, 0.f);
    out[(size_t)n * ostride + c] = v;
}

// ---------------- host orchestration ----------------
static void run_layer(const float* in, int lda, int K,
                      const float* W, const float* asrc, const float* adst,
                      const float* bias, int M, int C, int logC,
                      const int* src, const int* dst,
                      float* hw, float* xout, int ostride, int dorelu,
                      float* p_as, float* p_ad, float* p_emax, float* p_den,
                      float* p_e, float* p_agg) {
    dim3 gg(M / 64, (NN + 127) / 128);
    gemm_k<<<gg, 256>>>(in, lda, W, hw, NN, K, M);
    node_prep_k<<<(NN * HEADS + 255) / 256, 256>>>(hw, asrc, adst, p_as, p_ad,
                                                   p_emax, p_den, NN, C);
    cudaMemsetAsync(p_agg, 0, (size_t)NN * M * sizeof(float), 0);
    edge_max_k<<<(EE + 255) / 256, 256>>>(src, dst, p_as, p_ad, p_e, p_emax, EE);
    edge_exp_k<<<(EE + 255) / 256, 256>>>(dst, p_e, p_emax, p_den, EE);
    edge_agg_k<<<(EE * 32 + 255) / 256, 256>>>(src, dst, p_e, p_den, hw, p_agg,
                                               EE, M, logC);
    finalize_k<<<((size_t)NN * M + 255) / 256, 256>>>(p_agg, bias, xout, NN, M,
                                                      ostride, dorelu);
}

extern "C" void kernel_launch(void* const* d_in, const int* in_sizes, int n_in,
                              void* d_out, int out_size) {
    const float* x        = (const float*)d_in[0];
    const void*  ei       = d_in[1];
    const float* W1       = (const float*)d_in[2];
    const float* a_src1   = (const float*)d_in[3];
    const float* a_dst1   = (const float*)d_in[4];
    const float* b1       = (const float*)d_in[5];
    const float* W2       = (const float*)d_in[6];
    const float* a_src2   = (const float*)d_in[7];
    const float* a_dst2   = (const float*)d_in[8];
    const float* b2       = (const float*)d_in[9];
    const float* W3       = (const float*)d_in[10];
    const float* a_src3   = (const float*)d_in[11];
    const float* a_dst3   = (const float*)d_in[12];
    const float* b3       = (const float*)d_in[13];
    float* out = (float*)d_out;

    float *p_hw, *p_x, *p_agg, *p_as, *p_ad, *p_emax, *p_den, *p_e;
    int *p_src, *p_dst;
    cudaGetSymbolAddress((void**)&p_hw, g_hw);
    cudaGetSymbolAddress((void**)&p_x, g_x);
    cudaGetSymbolAddress((void**)&p_agg, g_agg);
    cudaGetSymbolAddress((void**)&p_as, g_as);
    cudaGetSymbolAddress((void**)&p_ad, g_ad);
    cudaGetSymbolAddress((void**)&p_emax, g_emax);
    cudaGetSymbolAddress((void**)&p_den, g_den);
    cudaGetSymbolAddress((void**)&p_e, g_e);
    cudaGetSymbolAddress((void**)&p_src, g_src);
    cudaGetSymbolAddress((void**)&p_dst, g_dst);

    // normalize edge indices to int32 (handles int32 or int64 input)
    detect_k<<<1, 256>>>(ei);
    convert_k<<<(EE + 255) / 256, 256>>>(ei);

    for (int t = 0; t < TT; t++) {
        // layer 1: input x[:, t, :] (stride T*IN_DIM), K=128 -> M=256, relu
        run_layer(x + (size_t)t * IN_DIM, TT * IN_DIM, IN_DIM,
                  W1, a_src1, a_dst1, b1, HID, HID / HEADS, 6,
                  p_src, p_dst, p_hw, p_x, HID, 1,
                  p_as, p_ad, p_emax, p_den, p_e, p_agg);
        // layer 2: K=256 -> M=256, relu
        run_layer(p_x, HID, HID,
                  W2, a_src2, a_dst2, b2, HID, HID / HEADS, 6,
                  p_src, p_dst, p_hw, p_x, HID, 1,
                  p_as, p_ad, p_emax, p_den, p_e, p_agg);
        // layer 3: K=256 -> M=128, no relu, write to d_out[:, t, :]
        run_layer(p_x, HID, HID,
                  W3, a_src3, a_dst3, b3, OUTD, OUTD / HEADS, 5,
                  p_src, p_dst, p_hw, out + (size_t)t * OUTD, TT * OUTD, 0,
                  p_as, p_ad, p_emax, p_den, p_e, p_agg);
    }
}

// round 3
// speedup vs baseline: 1.6191x; 1.6191x over previous
#include <cuda_runtime.h>
#include <math_constants.h>
#include <cstdint>

// ---------------- problem constants ----------------
#define NN      20000       // nodes
#define EE      320000      // edges
#define TT      12          // timesteps
#define IN_DIM  128
#define HID     256
#define OUTD    128
#define HEADS   4
#define NEG     0.2f

// ---------------- device scratch (no allocations allowed) ----------------
__device__ float4 g_hw4[(size_t)NN * HID / 4];   // h = x @ W (per layer)
__device__ float4 g_x4 [(size_t)NN * HID / 4];   // layer input / relu output
__device__ float  g_as [NN * HEADS];
__device__ float  g_ad [NN * HEADS];
__device__ float4 g_w4 [EE];                     // per-CSR-slot logits -> weights
__device__ int    g_src [EE];
__device__ int    g_dst [EE];
__device__ int    g_cnt [NN];
__device__ int    g_roff[NN + 1];
__device__ int    g_cur [NN];
__device__ int    g_eid [EE];
__device__ int    g_is64;

// ---------------- edge-index dtype detection + normalization ----------------
__global__ void detect_k(const void* ei) {
    __shared__ int bad;
    if (threadIdx.x == 0) bad = 0;
    __syncthreads();
    const long long* p = (const long long*)ei;
    for (int i = threadIdx.x; i < 2048; i += blockDim.x) {
        long long v = p[i];
        if (v < 0 || v >= NN) bad = 1;
    }
    __syncthreads();
    if (threadIdx.x == 0) g_is64 = bad ? 0 : 1;
}

__global__ void convert_k(const void* ei) {
    int i = blockIdx.x * blockDim.x + threadIdx.x;
    if (i >= EE) return;
    if (g_is64) {
        const long long* p = (const long long*)ei;
        g_src[i] = (int)p[i];
        g_dst[i] = (int)p[EE + i];
    } else {
        const int* p = (const int*)ei;
        g_src[i] = p[i];
        g_dst[i] = p[EE + i];
    }
}

// ---------------- CSR build (by dst) ----------------
__global__ void hist_k(const int* __restrict__ dst, int* __restrict__ cnt) {
    int e = blockIdx.x * blockDim.x + threadIdx.x;
    if (e < EE) atomicAdd(&cnt[dst[e]], 1);
}

__global__ void scan_k(const int* __restrict__ cnt, int* __restrict__ roff) {
    __shared__ int part[1024];
    const int chunk = (NN + 1023) / 1024;
    int t = threadIdx.x;
    int lo = t * chunk;
    int hi = lo + chunk; if (hi > NN) hi = NN;
    int s = 0;
    for (int i = lo; i < hi; i++) s += cnt[i];
    part[t] = s;
    __syncthreads();
    for (int o = 1; o < 1024; o <<= 1) {
        int v = (t >= o) ? part[t - o] : 0;
        __syncthreads();
        part[t] += v;
        __syncthreads();
    }
    int base = (t == 0) ? 0 : part[t - 1];
    for (int i = lo; i < hi; i++) { roff[i] = base; base += cnt[i]; }
    if (t == 1023) roff[NN] = base;
}

__global__ void scatter_k(const int* __restrict__ dst, int* __restrict__ cur,
                          int* __restrict__ eid) {
    int e = blockIdx.x * blockDim.x + threadIdx.x;
    if (e >= EE) return;
    int p = atomicAdd(&cur[dst[e]], 1);
    eid[p] = e;
}

// ---------------- GEMM: C[N,M] = A[N,K](lda) * B[K,M] ----------------
// BM=128, BN=64, BK=16, 256 threads, thread tile 8x4 (proven in R2)
__global__ void gemm_k(const float* __restrict__ A, int lda,
                       const float* __restrict__ B,
                       float* __restrict__ C,
                       int Nrows, int K, int M) {
    __shared__ float As[16][128];
    __shared__ float Bs[16][64];
    const int tid = threadIdx.x;
    const int rm = blockIdx.y * 128;
    const int cn = blockIdx.x * 64;
    const int ty = tid >> 4;
    const int tx = tid & 15;

    float acc[8][4];
#pragma unroll
    for (int i = 0; i < 8; i++)
#pragma unroll
        for (int j = 0; j < 4; j++) acc[i][j] = 0.0f;

    for (int k0 = 0; k0 < K; k0 += 16) {
#pragma unroll
        for (int l = 0; l < 2; l++) {
            int idx = tid + l * 256;
            int r = idx >> 2;
            int q = idx & 3;
            float4 v = make_float4(0.f, 0.f, 0.f, 0.f);
            int grow = rm + r;
            if (grow < Nrows)
                v = *(const float4*)(A + (size_t)grow * lda + k0 + q * 4);
            As[q * 4 + 0][r] = v.x;
            As[q * 4 + 1][r] = v.y;
            As[q * 4 + 2][r] = v.z;
            As[q * 4 + 3][r] = v.w;
        }
        {
            int kr = tid >> 4;
            int c4 = tid & 15;
            float4 v = *(const float4*)(B + (size_t)(k0 + kr) * M + cn + c4 * 4);
            *(float4*)&Bs[kr][c4 * 4] = v;
        }
        __syncthreads();
#pragma unroll
        for (int k = 0; k < 16; k++) {
            float a[8], b[4];
#pragma unroll
            for (int i = 0; i < 8; i++) a[i] = As[k][ty * 8 + i];
#pragma unroll
            for (int j = 0; j < 4; j++) b[j] = Bs[k][tx * 4 + j];
#pragma unroll
            for (int i = 0; i < 8; i++)
#pragma unroll
                for (int j = 0; j < 4; j++) acc[i][j] += a[i] * b[j];
        }
        __syncthreads();
    }
#pragma unroll
    for (int i = 0; i < 8; i++) {
        int grow = rm + ty * 8 + i;
        if (grow < Nrows) {
            float4 v = make_float4(acc[i][0], acc[i][1], acc[i][2], acc[i][3]);
            *(float4*)(C + (size_t)grow * M + cn + tx * 4) = v;
        }
    }
}

// ---------------- per-node attention logits (warp per node, coalesced) -----
template<int M>
__global__ void node_prep_k(const float* __restrict__ hw,
                            const float* __restrict__ a_src,
                            const float* __restrict__ a_dst,
                            float* __restrict__ as_, float* __restrict__ ad_) {
    constexpr int NC = M / 32;       // floats per lane
    constexpr int C = M / 4;         // channels per head
    int warp = (blockIdx.x * blockDim.x + threadIdx.x) >> 5;
    int lane = threadIdx.x & 31;
    if (warp >= NN) return;
    int g = lane >> 3;               // head handled by this lane group
    int cb = (lane & 7) * NC;        // col offset within head
    const float* hp = hw + (size_t)warp * M + g * C + cb;
    const float* sp = a_src + g * C + cb;
    const float* dp = a_dst + g * C + cb;
    float vs = 0.f, vd = 0.f;
#pragma unroll
    for (int j = 0; j < NC; j++) {
        float x = hp[j];
        vs += x * sp[j];
        vd += x * dp[j];
    }
#pragma unroll
    for (int o = 1; o < 8; o <<= 1) {
        vs += __shfl_xor_sync(0xffffffffu, vs, o);
        vd += __shfl_xor_sync(0xffffffffu, vd, o);
    }
    if ((lane & 7) == 0) {
        as_[warp * 4 + g] = vs;
        ad_[warp * 4 + g] = vd;
    }
}

// ---------------- fused softmax + gather aggregation (warp per node) -------
template<int M, int DORELU>
__global__ void gat_node_k(const int* __restrict__ roff,
                           const int* __restrict__ eid,
                           const int* __restrict__ src,
                           const float* __restrict__ as_,
                           const float* __restrict__ ad_,
                           const float* __restrict__ hw,
                           float* __restrict__ wbuf,   // EE*4 floats, 16B aligned
                           const float* __restrict__ bias,
                           float* __restrict__ out, int ostride) {
    constexpr int NC = M / 32;
    int warp = (blockIdx.x * blockDim.x + threadIdx.x) >> 5;
    int lane = threadIdx.x & 31;
    if (warp >= NN) return;
    const int n = warp;
    const int beg = roff[n], end = roff[n + 1];
    const int h = lane & 3, slot = lane >> 2;

    // phase 1: logits + per-head max (lane (slot,h) handles edge slots)
    float adv = ad_[n * 4 + h];
    float mx = -CUDART_INF_F;
    for (int i = beg + slot; i < end; i += 8) {
        int s = src[eid[i]];
        float v = as_[s * 4 + h] + adv;
        v = (v > 0.f) ? v : NEG * v;
        wbuf[(size_t)i * 4 + h] = v;
        mx = fmaxf(mx, v);
    }
    mx = fmaxf(mx, __shfl_xor_sync(0xffffffffu, mx, 4));
    mx = fmaxf(mx, __shfl_xor_sync(0xffffffffu, mx, 8));
    mx = fmaxf(mx, __shfl_xor_sync(0xffffffffu, mx, 16));

    // phase 2: exp + denom (store weights back)
    float den = 0.f;
    for (int i = beg + slot; i < end; i += 8) {
        float w = expf(wbuf[(size_t)i * 4 + h] - mx);
        wbuf[(size_t)i * 4 + h] = w;
        den += w;
    }
    den += __shfl_xor_sync(0xffffffffu, den, 4);
    den += __shfl_xor_sync(0xffffffffu, den, 8);
    den += __shfl_xor_sync(0xffffffffu, den, 16);
    den += 1e-16f;
    __threadfence_block();
    __syncwarp();

    // phase 3: weighted gather; lane handles NC contiguous cols
    const int hh = lane >> 3;   // head of this lane's columns (C = M/4, NC = C/8)
    float dinv = 1.0f / __shfl_sync(0xffffffffu, den, hh);
    float acc[NC];
#pragma unroll
    for (int j = 0; j < NC; j++) acc[j] = 0.f;
    const int colbase = lane * NC;
    for (int i = beg; i < end; i++) {
        int s = src[eid[i]];
        float4 w4 = *(const float4*)(wbuf + (size_t)i * 4);
        float wv = (hh == 0) ? w4.x : (hh == 1) ? w4.y : (hh == 2) ? w4.z : w4.w;
        float a = wv * dinv;
        const float* hp = hw + (size_t)s * M + colbase;
#pragma unroll
        for (int j = 0; j < NC; j += 4) {
            float4 v = *(const float4*)(hp + j);
            acc[j + 0] += a * v.x;
            acc[j + 1] += a * v.y;
            acc[j + 2] += a * v.z;
            acc[j + 3] += a * v.w;
        }
    }
    float* op = out + (size_t)n * ostride + colbase;
    const float* bp = bias + colbase;
#pragma unroll
    for (int j = 0; j < NC; j++) {
        float v = acc[j] + bp[j];
        if (DORELU) v = fmaxf(v, 0.f);
        op[j] = v;
    }
}

// ---------------- host orchestration ----------------
extern "C" void kernel_launch(void* const* d_in, const int* in_sizes, int n_in,
                              void* d_out, int out_size) {
    const float* x      = (const float*)d_in[0];
    const void*  ei     = d_in[1];
    const float* W1     = (const float*)d_in[2];
    const float* a_src1 = (const float*)d_in[3];
    const float* a_dst1 = (const float*)d_in[4];
    const float* b1     = (const float*)d_in[5];
    const float* W2     = (const float*)d_in[6];
    const float* a_src2 = (const float*)d_in[7];
    const float* a_dst2 = (const float*)d_in[8];
    const float* b2     = (const float*)d_in[9];
    const float* W3     = (const float*)d_in[10];
    const float* a_src3 = (const float*)d_in[11];
    const float* a_dst3 = (const float*)d_in[12];
    const float* b3     = (const float*)d_in[13];
    float* out = (float*)d_out;

    float *p_hw, *p_x, *p_as, *p_ad, *p_w;
    int *p_src, *p_dst, *p_cnt, *p_roff, *p_cur, *p_eid;
    cudaGetSymbolAddress((void**)&p_hw, g_hw4);
    cudaGetSymbolAddress((void**)&p_x, g_x4);
    cudaGetSymbolAddress((void**)&p_as, g_as);
    cudaGetSymbolAddress((void**)&p_ad, g_ad);
    cudaGetSymbolAddress((void**)&p_w, g_w4);
    cudaGetSymbolAddress((void**)&p_src, g_src);
    cudaGetSymbolAddress((void**)&p_dst, g_dst);
    cudaGetSymbolAddress((void**)&p_cnt, g_cnt);
    cudaGetSymbolAddress((void**)&p_roff, g_roff);
    cudaGetSymbolAddress((void**)&p_cur, g_cur);
    cudaGetSymbolAddress((void**)&p_eid, g_eid);

    // --- edge preprocessing: dtype normalize + CSR by dst ---
    detect_k<<<1, 256>>>(ei);
    convert_k<<<(EE + 255) / 256, 256>>>(ei);
    cudaMemsetAsync(p_cnt, 0, NN * sizeof(int), 0);
    hist_k<<<(EE + 255) / 256, 256>>>(p_dst, p_cnt);
    scan_k<<<1, 1024>>>(p_cnt, p_roff);
    cudaMemcpyAsync(p_cur, p_roff, NN * sizeof(int), cudaMemcpyDeviceToDevice, 0);
    scatter_k<<<(EE + 255) / 256, 256>>>(p_dst, p_cur, p_eid);

    const int npblk = (NN * 32 + 255) / 256;   // warp-per-node grids
    for (int t = 0; t < TT; t++) {
        // ---- layer 1: K=128 -> M=256, relu -> g_x ----
        {
            dim3 gg(HID / 64, (NN + 127) / 128);
            gemm_k<<<gg, 256>>>(x + (size_t)t * IN_DIM, TT * IN_DIM, W1, p_hw,
                                NN, IN_DIM, HID);
            node_prep_k<HID><<<npblk, 256>>>(p_hw, a_src1, a_dst1, p_as, p_ad);
            gat_node_k<HID, 1><<<npblk, 256>>>(p_roff, p_eid, p_src, p_as, p_ad,
                                               p_hw, p_w, b1, p_x, HID);
        }
        // ---- layer 2: K=256 -> M=256, relu -> g_x ----
        {
            dim3 gg(HID / 64, (NN + 127) / 128);
            gemm_k<<<gg, 256>>>(p_x, HID, W2, p_hw, NN, HID, HID);
            node_prep_k<HID><<<npblk, 256>>>(p_hw, a_src2, a_dst2, p_as, p_ad);
            gat_node_k<HID, 1><<<npblk, 256>>>(p_roff, p_eid, p_src, p_as, p_ad,
                                               p_hw, p_w, b2, p_x, HID);
        }
        // ---- layer 3: K=256 -> M=128, no relu -> d_out[:, t, :] ----
        {
            dim3 gg(OUTD / 64, (NN + 127) / 128);
            gemm_k<<<gg, 256>>>(p_x, HID, W3, p_hw, NN, HID, OUTD);
            node_prep_k<OUTD><<<npblk, 256>>>(p_hw, a_src3, a_dst3, p_as, p_ad);
            gat_node_k<OUTD, 0><<<npblk, 256>>>(p_roff, p_eid, p_src, p_as, p_ad,
                                                p_hw, p_w, b3,
                                                out + (size_t)t * OUTD, TT * OUTD);
        }
    }
}

// round 4
// speedup vs baseline: 1.6814x; 1.0384x over previous
#include <cuda_runtime.h>
#include <math_constants.h>
#include <cstdint>

// ---------------- problem constants ----------------
#define NN      20000
#define EE      320000
#define TT      12
#define IN_DIM  128
#define HID     256
#define OUTD    128
#define HEADS   4
#define NEG     0.2f

// ---------------- device scratch ----------------
__device__ float4 g_hw4[(size_t)NN * HID / 4];
__device__ float4 g_x4 [(size_t)NN * HID / 4];
__device__ float  g_as [NN * HEADS];
__device__ float  g_ad [NN * HEADS];
__device__ float4 g_w4 [EE];
__device__ int    g_src [EE];
__device__ int    g_dst [EE];
__device__ int    g_cnt [NN];
__device__ int    g_roff[NN + 1];
__device__ int    g_cur [NN];
__device__ int    g_eid [EE];
__device__ int    g_is64;

// ---------------- edge-index dtype detection + normalization ----------------
__global__ void detect_k(const void* ei) {
    __shared__ int bad;
    if (threadIdx.x == 0) bad = 0;
    __syncthreads();
    const long long* p = (const long long*)ei;
    for (int i = threadIdx.x; i < 2048; i += blockDim.x) {
        long long v = p[i];
        if (v < 0 || v >= NN) bad = 1;
    }
    __syncthreads();
    if (threadIdx.x == 0) g_is64 = bad ? 0 : 1;
}

__global__ void convert_k(const void* ei) {
    int i = blockIdx.x * blockDim.x + threadIdx.x;
    if (i >= EE) return;
    if (g_is64) {
        const long long* p = (const long long*)ei;
        g_src[i] = (int)p[i];
        g_dst[i] = (int)p[EE + i];
    } else {
        const int* p = (const int*)ei;
        g_src[i] = p[i];
        g_dst[i] = p[EE + i];
    }
}

// ---------------- CSR build (by dst) ----------------
__global__ void hist_k(const int* __restrict__ dst, int* __restrict__ cnt) {
    int e = blockIdx.x * blockDim.x + threadIdx.x;
    if (e < EE) atomicAdd(&cnt[dst[e]], 1);
}

__global__ void scan_k(const int* __restrict__ cnt, int* __restrict__ roff) {
    __shared__ int part[1024];
    const int chunk = (NN + 1023) / 1024;
    int t = threadIdx.x;
    int lo = t * chunk;
    int hi = lo + chunk; if (hi > NN) hi = NN;
    int s = 0;
    for (int i = lo; i < hi; i++) s += cnt[i];
    part[t] = s;
    __syncthreads();
    for (int o = 1; o < 1024; o <<= 1) {
        int v = (t >= o) ? part[t - o] : 0;
        __syncthreads();
        part[t] += v;
        __syncthreads();
    }
    int base = (t == 0) ? 0 : part[t - 1];
    for (int i = lo; i < hi; i++) { roff[i] = base; base += cnt[i]; }
    if (t == 1023) roff[NN] = base;
}

__global__ void scatter_k(const int* __restrict__ dst, int* __restrict__ cur,
                          int* __restrict__ eid) {
    int e = blockIdx.x * blockDim.x + threadIdx.x;
    if (e >= EE) return;
    int p = atomicAdd(&cur[dst[e]], 1);
    eid[p] = e;
}

// ---------------- TF32 helpers ----------------
__device__ __forceinline__ uint32_t f2tf32(float f) {
    uint32_t u;
    asm("cvt.rna.tf32.f32 %0, %1;" : "=r"(u) : "f"(f));
    return u;
}
__device__ __forceinline__ void split_tf32(float f, uint32_t& hi, uint32_t& lo) {
    hi = f2tf32(f);
    float r = f - __uint_as_float(hi);
    lo = f2tf32(r);
}
__device__ __forceinline__ void mma_tf32(float* c, uint32_t a0, uint32_t a1,
                                         uint32_t a2, uint32_t a3,
                                         uint32_t b0, uint32_t b1) {
    asm volatile(
        "mma.sync.aligned.m16n8k8.row.col.f32.tf32.tf32.f32 "
        "{%0,%1,%2,%3}, {%4,%5,%6,%7}, {%8,%9}, {%0,%1,%2,%3};"
        : "+f"(c[0]), "+f"(c[1]), "+f"(c[2]), "+f"(c[3])
        : "r"(a0), "r"(a1), "r"(a2), "r"(a3), "r"(b0), "r"(b1));
}

// ---------------- GEMM: C[N,M] = A[N,K](lda) * B[K,M], 3xTF32 ----------------
// BM=128, BN=128, BK=32, 256 threads = 8 warps (2m x 4n), warp tile 64x32
__global__ __launch_bounds__(256, 1)
void gemm_tc_k(const float* __restrict__ A, int lda,
               const float* __restrict__ B,
               float* __restrict__ C,
               int Nrows, int K, int M) {
    __shared__ float As[128][36];   // [m][k], pad 4 -> conflict-free frag loads
    __shared__ float Bs[32][132];   // [k][n]

    const int tid = threadIdx.x;
    const int wid = tid >> 5;
    const int lane = tid & 31;
    const int gid = lane >> 2;      // 0..7
    const int t4 = lane & 3;        // 0..3
    const int rm = blockIdx.y * 128;
    const int cn = blockIdx.x * 128;
    const int wm = (wid & 1) * 64;  // warp m offset in tile
    const int wn = (wid >> 1) * 32; // warp n offset in tile

    float acc[4][4][4];
#pragma unroll
    for (int i = 0; i < 4; i++)
#pragma unroll
        for (int j = 0; j < 4; j++)
#pragma unroll
            for (int q = 0; q < 4; q++) acc[i][j][q] = 0.f;

    const int ar = tid >> 3;         // 0..31 base row for A loads
    const int af = tid & 7;          // float4 index within 32-col row
    const int bk = tid >> 5;         // 0..7 base k for B loads
    const int bn = (tid & 31) * 4;   // n offset for B loads

    for (int k0 = 0; k0 < K; k0 += 32) {
        // load A tile (128x32): 4 float4 per thread
#pragma unroll
        for (int l = 0; l < 4; l++) {
            int row = ar + 32 * l;
            int grow = rm + row;
            float4 v = make_float4(0.f, 0.f, 0.f, 0.f);
            if (grow < Nrows)
                v = *(const float4*)(A + (size_t)grow * lda + k0 + af * 4);
            *(float4*)&As[row][af * 4] = v;
        }
        // load B tile (32x128): 4 float4 per thread, direct [k][n]
#pragma unroll
        for (int l = 0; l < 4; l++) {
            int kr = bk + 8 * l;
            float4 v = *(const float4*)(B + (size_t)(k0 + kr) * M + cn + bn);
            *(float4*)&Bs[kr][bn] = v;
        }
        __syncthreads();

#pragma unroll
        for (int kk = 0; kk < 4; kk++) {
            const int k8 = kk * 8;
            uint32_t ah[4][4], al[4][4], bh[4][2], bl[4][2];
#pragma unroll
            for (int ma = 0; ma < 4; ma++) {
                int m = wm + ma * 16;
                split_tf32(As[m + gid][k8 + t4],         ah[ma][0], al[ma][0]);
                split_tf32(As[m + gid + 8][k8 + t4],     ah[ma][1], al[ma][1]);
                split_tf32(As[m + gid][k8 + t4 + 4],     ah[ma][2], al[ma][2]);
                split_tf32(As[m + gid + 8][k8 + t4 + 4], ah[ma][3], al[ma][3]);
            }
#pragma unroll
            for (int nb = 0; nb < 4; nb++) {
                int n = wn + nb * 8;
                split_tf32(Bs[k8 + t4][n + gid],     bh[nb][0], bl[nb][0]);
                split_tf32(Bs[k8 + t4 + 4][n + gid], bh[nb][1], bl[nb][1]);
            }
#pragma unroll
            for (int ma = 0; ma < 4; ma++)
#pragma unroll
                for (int nb = 0; nb < 4; nb++) {
                    float* c = acc[ma][nb];
                    mma_tf32(c, ah[ma][0], ah[ma][1], ah[ma][2], ah[ma][3],
                             bh[nb][0], bh[nb][1]);
                    mma_tf32(c, ah[ma][0], ah[ma][1], ah[ma][2], ah[ma][3],
                             bl[nb][0], bl[nb][1]);
                    mma_tf32(c, al[ma][0], al[ma][1], al[ma][2], al[ma][3],
                             bh[nb][0], bh[nb][1]);
                }
        }
        __syncthreads();
    }

    // epilogue
#pragma unroll
    for (int ma = 0; ma < 4; ma++) {
        int r0 = rm + wm + ma * 16 + gid;
        int r1 = r0 + 8;
#pragma unroll
        for (int nb = 0; nb < 4; nb++) {
            int col = cn + wn + nb * 8 + 2 * t4;
            if (r0 < Nrows)
                *(float2*)(C + (size_t)r0 * M + col) =
                    make_float2(acc[ma][nb][0], acc[ma][nb][1]);
            if (r1 < Nrows)
                *(float2*)(C + (size_t)r1 * M + col) =
                    make_float2(acc[ma][nb][2], acc[ma][nb][3]);
        }
    }
}

// ---------------- per-node attention logits (warp per node) ----------------
template<int M>
__global__ void node_prep_k(const float* __restrict__ hw,
                            const float* __restrict__ a_src,
                            const float* __restrict__ a_dst,
                            float* __restrict__ as_, float* __restrict__ ad_) {
    constexpr int NC = M / 32;
    constexpr int C = M / 4;
    int warp = (blockIdx.x * blockDim.x + threadIdx.x) >> 5;
    int lane = threadIdx.x & 31;
    if (warp >= NN) return;
    int g = lane >> 3;
    int cb = (lane & 7) * NC;
    const float* hp = hw + (size_t)warp * M + g * C + cb;
    const float* sp = a_src + g * C + cb;
    const float* dp = a_dst + g * C + cb;
    float vs = 0.f, vd = 0.f;
#pragma unroll
    for (int j = 0; j < NC; j++) {
        float x = hp[j];
        vs += x * sp[j];
        vd += x * dp[j];
    }
#pragma unroll
    for (int o = 1; o < 8; o <<= 1) {
        vs += __shfl_xor_sync(0xffffffffu, vs, o);
        vd += __shfl_xor_sync(0xffffffffu, vd, o);
    }
    if ((lane & 7) == 0) {
        as_[warp * 4 + g] = vs;
        ad_[warp * 4 + g] = vd;
    }
}

// ---------------- fused softmax + gather aggregation (warp per node) -------
template<int M, int DORELU>
__global__ void gat_node_k(const int* __restrict__ roff,
                           const int* __restrict__ eid,
                           const int* __restrict__ src,
                           const float* __restrict__ as_,
                           const float* __restrict__ ad_,
                           const float* __restrict__ hw,
                           float* __restrict__ wbuf,
                           const float* __restrict__ bias,
                           float* __restrict__ out, int ostride) {
    constexpr int NC = M / 32;
    int warp = (blockIdx.x * blockDim.x + threadIdx.x) >> 5;
    int lane = threadIdx.x & 31;
    if (warp >= NN) return;
    const int n = warp;
    const int beg = roff[n], end = roff[n + 1];
    const int h = lane & 3, slot = lane >> 2;

    float adv = ad_[n * 4 + h];
    float mx = -CUDART_INF_F;
    for (int i = beg + slot; i < end; i += 8) {
        int s = src[eid[i]];
        float v = as_[s * 4 + h] + adv;
        v = (v > 0.f) ? v : NEG * v;
        wbuf[(size_t)i * 4 + h] = v;
        mx = fmaxf(mx, v);
    }
    mx = fmaxf(mx, __shfl_xor_sync(0xffffffffu, mx, 4));
    mx = fmaxf(mx, __shfl_xor_sync(0xffffffffu, mx, 8));
    mx = fmaxf(mx, __shfl_xor_sync(0xffffffffu, mx, 16));

    float den = 0.f;
    for (int i = beg + slot; i < end; i += 8) {
        float w = expf(wbuf[(size_t)i * 4 + h] - mx);
        wbuf[(size_t)i * 4 + h] = w;
        den += w;
    }
    den += __shfl_xor_sync(0xffffffffu, den, 4);
    den += __shfl_xor_sync(0xffffffffu, den, 8);
    den += __shfl_xor_sync(0xffffffffu, den, 16);
    den += 1e-16f;
    __threadfence_block();
    __syncwarp();

    const int hh = lane >> 3;
    float dinv = 1.0f / __shfl_sync(0xffffffffu, den, hh);
    float acc[NC];
#pragma unroll
    for (int j = 0; j < NC; j++) acc[j] = 0.f;
    const int colbase = lane * NC;
    for (int i = beg; i < end; i++) {
        int s = src[eid[i]];
        float4 w4 = *(const float4*)(wbuf + (size_t)i * 4);
        float wv = (hh == 0) ? w4.x : (hh == 1) ? w4.y : (hh == 2) ? w4.z : w4.w;
        float a = wv * dinv;
        const float* hp = hw + (size_t)s * M + colbase;
#pragma unroll
        for (int j = 0; j < NC; j += 4) {
            float4 v = *(const float4*)(hp + j);
            acc[j + 0] += a * v.x;
            acc[j + 1] += a * v.y;
            acc[j + 2] += a * v.z;
            acc[j + 3] += a * v.w;
        }
    }
    float* op = out + (size_t)n * ostride + colbase;
    const float* bp = bias + colbase;
#pragma unroll
    for (int j = 0; j < NC; j++) {
        float v = acc[j] + bp[j];
        if (DORELU) v = fmaxf(v, 0.f);
        op[j] = v;
    }
}

// ---------------- host orchestration ----------------
extern "C" void kernel_launch(void* const* d_in, const int* in_sizes, int n_in,
                              void* d_out, int out_size) {
    const float* x      = (const float*)d_in[0];
    const void*  ei     = d_in[1];
    const float* W1     = (const float*)d_in[2];
    const float* a_src1 = (const float*)d_in[3];
    const float* a_dst1 = (const float*)d_in[4];
    const float* b1     = (const float*)d_in[5];
    const float* W2     = (const float*)d_in[6];
    const float* a_src2 = (const float*)d_in[7];
    const float* a_dst2 = (const float*)d_in[8];
    const float* b2     = (const float*)d_in[9];
    const float* W3     = (const float*)d_in[10];
    const float* a_src3 = (const float*)d_in[11];
    const float* a_dst3 = (const float*)d_in[12];
    const float* b3     = (const float*)d_in[13];
    float* out = (float*)d_out;

    float *p_hw, *p_x, *p_as, *p_ad, *p_w;
    int *p_src, *p_dst, *p_cnt, *p_roff, *p_cur, *p_eid;
    cudaGetSymbolAddress((void**)&p_hw, g_hw4);
    cudaGetSymbolAddress((void**)&p_x, g_x4);
    cudaGetSymbolAddress((void**)&p_as, g_as);
    cudaGetSymbolAddress((void**)&p_ad, g_ad);
    cudaGetSymbolAddress((void**)&p_w, g_w4);
    cudaGetSymbolAddress((void**)&p_src, g_src);
    cudaGetSymbolAddress((void**)&p_dst, g_dst);
    cudaGetSymbolAddress((void**)&p_cnt, g_cnt);
    cudaGetSymbolAddress((void**)&p_roff, g_roff);
    cudaGetSymbolAddress((void**)&p_cur, g_cur);
    cudaGetSymbolAddress((void**)&p_eid, g_eid);

    detect_k<<<1, 256>>>(ei);
    convert_k<<<(EE + 255) / 256, 256>>>(ei);
    cudaMemsetAsync(p_cnt, 0, NN * sizeof(int), 0);
    hist_k<<<(EE + 255) / 256, 256>>>(p_dst, p_cnt);
    scan_k<<<1, 1024>>>(p_cnt, p_roff);
    cudaMemcpyAsync(p_cur, p_roff, NN * sizeof(int), cudaMemcpyDeviceToDevice, 0);
    scatter_k<<<(EE + 255) / 256, 256>>>(p_dst, p_cur, p_eid);

    const int npblk = (NN * 32 + 255) / 256;
    const int rowblk = (NN + 127) / 128;
    for (int t = 0; t < TT; t++) {
        {
            dim3 gg(HID / 128, rowblk);
            gemm_tc_k<<<gg, 256>>>(x + (size_t)t * IN_DIM, TT * IN_DIM, W1,
                                   p_hw, NN, IN_DIM, HID);
            node_prep_k<HID><<<npblk, 256>>>(p_hw, a_src1, a_dst1, p_as, p_ad);
            gat_node_k<HID, 1><<<npblk, 256>>>(p_roff, p_eid, p_src, p_as, p_ad,
                                               p_hw, p_w, b1, p_x, HID);
        }
        {
            dim3 gg(HID / 128, rowblk);
            gemm_tc_k<<<gg, 256>>>(p_x, HID, W2, p_hw, NN, HID, HID);
            node_prep_k<HID><<<npblk, 256>>>(p_hw, a_src2, a_dst2, p_as, p_ad);
            gat_node_k<HID, 1><<<npblk, 256>>>(p_roff, p_eid, p_src, p_as, p_ad,
                                               p_hw, p_w, b2, p_x, HID);
        }
        {
            dim3 gg(OUTD / 128, rowblk);
            gemm_tc_k<<<gg, 256>>>(p_x, HID, W3, p_hw, NN, HID, OUTD);
            node_prep_k<OUTD><<<npblk, 256>>>(p_hw, a_src3, a_dst3, p_as, p_ad);
            gat_node_k<OUTD, 0><<<npblk, 256>>>(p_roff, p_eid, p_src, p_as, p_ad,
                                                p_hw, p_w, b3,
                                                out + (size_t)t * OUTD, TT * OUTD);
        }
    }
}

// round 5
// speedup vs baseline: 2.2992x; 1.3675x over previous
#include <cuda_runtime.h>
#include <math_constants.h>
#include <cstdint>

// ---------------- problem constants ----------------
#define NN      20000
#define EE      320000
#define TT      12
#define IN_DIM  128
#define HID     256
#define OUTD    128
#define HEADS   4
#define NEG     0.2f
#define NCHAIN  4

// ---------------- device scratch (per-chain) ----------------
__device__ float4 g_hw4[NCHAIN][(size_t)NN * HID / 4];
__device__ float4 g_x4 [NCHAIN][(size_t)NN * HID / 4];
__device__ float4 g_w4 [NCHAIN][EE];
__device__ float  g_as [NCHAIN][NN * HEADS];
__device__ float  g_ad [NCHAIN][NN * HEADS];
__device__ int    g_src [EE];
__device__ int    g_dst [EE];
__device__ int    g_cnt [NN];
__device__ int    g_roff[NN + 1];
__device__ int    g_cur [NN];
__device__ int    g_eid [EE];
__device__ int    g_is64;

// ---------------- edge-index dtype detection + normalization ----------------
__global__ void detect_k(const void* ei) {
    __shared__ int bad;
    if (threadIdx.x == 0) bad = 0;
    __syncthreads();
    const long long* p = (const long long*)ei;
    for (int i = threadIdx.x; i < 2048; i += blockDim.x) {
        long long v = p[i];
        if (v < 0 || v >= NN) bad = 1;
    }
    __syncthreads();
    if (threadIdx.x == 0) g_is64 = bad ? 0 : 1;
}

__global__ void convert_k(const void* ei) {
    int i = blockIdx.x * blockDim.x + threadIdx.x;
    if (i >= EE) return;
    if (g_is64) {
        const long long* p = (const long long*)ei;
        g_src[i] = (int)p[i];
        g_dst[i] = (int)p[EE + i];
    } else {
        const int* p = (const int*)ei;
        g_src[i] = p[i];
        g_dst[i] = p[EE + i];
    }
}

// ---------------- CSR build (by dst) ----------------
__global__ void hist_k(const int* __restrict__ dst, int* __restrict__ cnt) {
    int e = blockIdx.x * blockDim.x + threadIdx.x;
    if (e < EE) atomicAdd(&cnt[dst[e]], 1);
}

__global__ void scan_k(const int* __restrict__ cnt, int* __restrict__ roff) {
    __shared__ int part[1024];
    const int chunk = (NN + 1023) / 1024;
    int t = threadIdx.x;
    int lo = t * chunk;
    int hi = lo + chunk; if (hi > NN) hi = NN;
    int s = 0;
    for (int i = lo; i < hi; i++) s += cnt[i];
    part[t] = s;
    __syncthreads();
    for (int o = 1; o < 1024; o <<= 1) {
        int v = (t >= o) ? part[t - o] : 0;
        __syncthreads();
        part[t] += v;
        __syncthreads();
    }
    int base = (t == 0) ? 0 : part[t - 1];
    for (int i = lo; i < hi; i++) { roff[i] = base; base += cnt[i]; }
    if (t == 1023) roff[NN] = base;
}

__global__ void scatter_k(const int* __restrict__ dst, int* __restrict__ cur,
                          int* __restrict__ eid) {
    int e = blockIdx.x * blockDim.x + threadIdx.x;
    if (e >= EE) return;
    int p = atomicAdd(&cur[dst[e]], 1);
    eid[p] = e;
}

// ---------------- TF32 helpers ----------------
__device__ __forceinline__ uint32_t f2tf32(float f) {
    uint32_t u;
    asm("cvt.rna.tf32.f32 %0, %1;" : "=r"(u) : "f"(f));
    return u;
}
__device__ __forceinline__ void mma_tf32(float* c, uint32_t a0, uint32_t a1,
                                         uint32_t a2, uint32_t a3,
                                         uint32_t b0, uint32_t b1) {
    asm volatile(
        "mma.sync.aligned.m16n8k8.row.col.f32.tf32.tf32.f32 "
        "{%0,%1,%2,%3}, {%4,%5,%6,%7}, {%8,%9}, {%0,%1,%2,%3};"
        : "+f"(c[0]), "+f"(c[1]), "+f"(c[2]), "+f"(c[3])
        : "r"(a0), "r"(a1), "r"(a2), "r"(a3), "r"(b0), "r"(b1));
}

// ---------------- GEMM: C[N,M] = A[N,K](lda) * B[K,M], 3xTF32 ----------------
// BM=128, BN=128, BK=32, 256 threads = 8 warps (2m x 4n), warp tile 64x32.
// Splits hoisted to load time: hi/lo smem tiles, inner loop = LDS + MMA only.
#define GEMM_SMEM ((2 * 128 * 36 + 2 * 32 * 132) * 4)
__global__ __launch_bounds__(256, 1)
void gemm_tc_k(const float* __restrict__ A, int lda,
               const float* __restrict__ B,
               float* __restrict__ C,
               int Nrows, int K, int M) {
    extern __shared__ float smem[];
    float (*Ah)[36]  = (float(*)[36])smem;                   // 128 x 36
    float (*Al)[36]  = (float(*)[36])(smem + 128 * 36);      // 128 x 36
    float (*Bh)[132] = (float(*)[132])(smem + 2 * 128 * 36); // 32 x 132
    float (*Bl)[132] = (float(*)[132])(smem + 2 * 128 * 36 + 32 * 132);

    const int tid = threadIdx.x;
    const int wid = tid >> 5;
    const int lane = tid & 31;
    const int gid = lane >> 2;
    const int t4 = lane & 3;
    const int rm = blockIdx.y * 128;
    const int cn = blockIdx.x * 128;
    const int wm = (wid & 1) * 64;
    const int wn = (wid >> 1) * 32;

    float acc[4][4][4];
#pragma unroll
    for (int i = 0; i < 4; i++)
#pragma unroll
        for (int j = 0; j < 4; j++)
#pragma unroll
            for (int q = 0; q < 4; q++) acc[i][j][q] = 0.f;

    const int ar = tid >> 3;
    const int af = tid & 7;
    const int bk = tid >> 5;
    const int bn = (tid & 31) * 4;

    for (int k0 = 0; k0 < K; k0 += 32) {
        // load + split A tile (128x32)
#pragma unroll
        for (int l = 0; l < 4; l++) {
            int row = ar + 32 * l;
            int grow = rm + row;
            float4 v = make_float4(0.f, 0.f, 0.f, 0.f);
            if (grow < Nrows)
                v = *(const float4*)(A + (size_t)grow * lda + k0 + af * 4);
            float* ph = &Ah[row][af * 4];
            float* pl = &Al[row][af * 4];
            uint32_t h0 = f2tf32(v.x), h1 = f2tf32(v.y),
                     h2 = f2tf32(v.z), h3 = f2tf32(v.w);
            ph[0] = __uint_as_float(h0); ph[1] = __uint_as_float(h1);
            ph[2] = __uint_as_float(h2); ph[3] = __uint_as_float(h3);
            pl[0] = __uint_as_float(f2tf32(v.x - __uint_as_float(h0)));
            pl[1] = __uint_as_float(f2tf32(v.y - __uint_as_float(h1)));
            pl[2] = __uint_as_float(f2tf32(v.z - __uint_as_float(h2)));
            pl[3] = __uint_as_float(f2tf32(v.w - __uint_as_float(h3)));
        }
        // load + split B tile (32x128)
#pragma unroll
        for (int l = 0; l < 4; l++) {
            int kr = bk + 8 * l;
            float4 v = *(const float4*)(B + (size_t)(k0 + kr) * M + cn + bn);
            float* ph = &Bh[kr][bn];
            float* pl = &Bl[kr][bn];
            uint32_t h0 = f2tf32(v.x), h1 = f2tf32(v.y),
                     h2 = f2tf32(v.z), h3 = f2tf32(v.w);
            ph[0] = __uint_as_float(h0); ph[1] = __uint_as_float(h1);
            ph[2] = __uint_as_float(h2); ph[3] = __uint_as_float(h3);
            pl[0] = __uint_as_float(f2tf32(v.x - __uint_as_float(h0)));
            pl[1] = __uint_as_float(f2tf32(v.y - __uint_as_float(h1)));
            pl[2] = __uint_as_float(f2tf32(v.z - __uint_as_float(h2)));
            pl[3] = __uint_as_float(f2tf32(v.w - __uint_as_float(h3)));
        }
        __syncthreads();

#pragma unroll
        for (int kk = 0; kk < 4; kk++) {
            const int k8 = kk * 8;
            uint32_t ah[4][4], al[4][4], bh[4][2], bl[4][2];
#pragma unroll
            for (int ma = 0; ma < 4; ma++) {
                int m = wm + ma * 16;
                ah[ma][0] = __float_as_uint(Ah[m + gid][k8 + t4]);
                ah[ma][1] = __float_as_uint(Ah[m + gid + 8][k8 + t4]);
                ah[ma][2] = __float_as_uint(Ah[m + gid][k8 + t4 + 4]);
                ah[ma][3] = __float_as_uint(Ah[m + gid + 8][k8 + t4 + 4]);
                al[ma][0] = __float_as_uint(Al[m + gid][k8 + t4]);
                al[ma][1] = __float_as_uint(Al[m + gid + 8][k8 + t4]);
                al[ma][2] = __float_as_uint(Al[m + gid][k8 + t4 + 4]);
                al[ma][3] = __float_as_uint(Al[m + gid + 8][k8 + t4 + 4]);
            }
#pragma unroll
            for (int nb = 0; nb < 4; nb++) {
                int n = wn + nb * 8;
                bh[nb][0] = __float_as_uint(Bh[k8 + t4][n + gid]);
                bh[nb][1] = __float_as_uint(Bh[k8 + t4 + 4][n + gid]);
                bl[nb][0] = __float_as_uint(Bl[k8 + t4][n + gid]);
                bl[nb][1] = __float_as_uint(Bl[k8 + t4 + 4][n + gid]);
            }
#pragma unroll
            for (int ma = 0; ma < 4; ma++)
#pragma unroll
                for (int nb = 0; nb < 4; nb++) {
                    float* c = acc[ma][nb];
                    mma_tf32(c, ah[ma][0], ah[ma][1], ah[ma][2], ah[ma][3],
                             bh[nb][0], bh[nb][1]);
                    mma_tf32(c, ah[ma][0], ah[ma][1], ah[ma][2], ah[ma][3],
                             bl[nb][0], bl[nb][1]);
                    mma_tf32(c, al[ma][0], al[ma][1], al[ma][2], al[ma][3],
                             bh[nb][0], bh[nb][1]);
                }
        }
        __syncthreads();
    }

#pragma unroll
    for (int ma = 0; ma < 4; ma++) {
        int r0 = rm + wm + ma * 16 + gid;
        int r1 = r0 + 8;
#pragma unroll
        for (int nb = 0; nb < 4; nb++) {
            int col = cn + wn + nb * 8 + 2 * t4;
            if (r0 < Nrows)
                *(float2*)(C + (size_t)r0 * M + col) =
                    make_float2(acc[ma][nb][0], acc[ma][nb][1]);
            if (r1 < Nrows)
                *(float2*)(C + (size_t)r1 * M + col) =
                    make_float2(acc[ma][nb][2], acc[ma][nb][3]);
        }
    }
}

// ---------------- per-node attention logits (warp per node) ----------------
template<int M>
__global__ void node_prep_k(const float* __restrict__ hw,
                            const float* __restrict__ a_src,
                            const float* __restrict__ a_dst,
                            float* __restrict__ as_, float* __restrict__ ad_) {
    constexpr int NC = M / 32;
    constexpr int C = M / 4;
    int warp = (blockIdx.x * blockDim.x + threadIdx.x) >> 5;
    int lane = threadIdx.x & 31;
    if (warp >= NN) return;
    int g = lane >> 3;
    int cb = (lane & 7) * NC;
    const float* hp = hw + (size_t)warp * M + g * C + cb;
    const float* sp = a_src + g * C + cb;
    const float* dp = a_dst + g * C + cb;
    float vs = 0.f, vd = 0.f;
#pragma unroll
    for (int j = 0; j < NC; j++) {
        float x = hp[j];
        vs += x * sp[j];
        vd += x * dp[j];
    }
#pragma unroll
    for (int o = 1; o < 8; o <<= 1) {
        vs += __shfl_xor_sync(0xffffffffu, vs, o);
        vd += __shfl_xor_sync(0xffffffffu, vd, o);
    }
    if ((lane & 7) == 0) {
        as_[warp * 4 + g] = vs;
        ad_[warp * 4 + g] = vd;
    }
}

// ---------------- fused softmax + gather aggregation (warp per node) -------
template<int M, int DORELU>
__global__ void gat_node_k(const int* __restrict__ roff,
                           const int* __restrict__ eid,
                           const int* __restrict__ src,
                           const float* __restrict__ as_,
                           const float* __restrict__ ad_,
                           const float* __restrict__ hw,
                           float* __restrict__ wbuf,
                           const float* __restrict__ bias,
                           float* __restrict__ out, int ostride) {
    constexpr int NC = M / 32;
    int warp = (blockIdx.x * blockDim.x + threadIdx.x) >> 5;
    int lane = threadIdx.x & 31;
    if (warp >= NN) return;
    const int n = warp;
    const int beg = roff[n], end = roff[n + 1];
    const int h = lane & 3, slot = lane >> 2;

    float adv = ad_[n * 4 + h];
    float mx = -CUDART_INF_F;
    for (int i = beg + slot; i < end; i += 8) {
        int s = src[eid[i]];
        float v = as_[s * 4 + h] + adv;
        v = (v > 0.f) ? v : NEG * v;
        wbuf[(size_t)i * 4 + h] = v;
        mx = fmaxf(mx, v);
    }
    mx = fmaxf(mx, __shfl_xor_sync(0xffffffffu, mx, 4));
    mx = fmaxf(mx, __shfl_xor_sync(0xffffffffu, mx, 8));
    mx = fmaxf(mx, __shfl_xor_sync(0xffffffffu, mx, 16));

    float den = 0.f;
    for (int i = beg + slot; i < end; i += 8) {
        float w = expf(wbuf[(size_t)i * 4 + h] - mx);
        wbuf[(size_t)i * 4 + h] = w;
        den += w;
    }
    den += __shfl_xor_sync(0xffffffffu, den, 4);
    den += __shfl_xor_sync(0xffffffffu, den, 8);
    den += __shfl_xor_sync(0xffffffffu, den, 16);
    den += 1e-16f;
    __threadfence_block();
    __syncwarp();

    const int hh = lane >> 3;
    float dinv = 1.0f / __shfl_sync(0xffffffffu, den, hh);
    float acc[NC];
#pragma unroll
    for (int j = 0; j < NC; j++) acc[j] = 0.f;
    const int colbase = lane * NC;
    for (int i = beg; i < end; i++) {
        int s = src[eid[i]];
        float4 w4 = *(const float4*)(wbuf + (size_t)i * 4);
        float wv = (hh == 0) ? w4.x : (hh == 1) ? w4.y : (hh == 2) ? w4.z : w4.w;
        float a = wv * dinv;
        const float* hp = hw + (size_t)s * M + colbase;
#pragma unroll
        for (int j = 0; j < NC; j += 4) {
            float4 v = *(const float4*)(hp + j);
            acc[j + 0] += a * v.x;
            acc[j + 1] += a * v.y;
            acc[j + 2] += a * v.z;
            acc[j + 3] += a * v.w;
        }
    }
    float* op = out + (size_t)n * ostride + colbase;
    const float* bp = bias + colbase;
#pragma unroll
    for (int j = 0; j < NC; j++) {
        float v = acc[j] + bp[j];
        if (DORELU) v = fmaxf(v, 0.f);
        op[j] = v;
    }
}

// ---------------- host orchestration ----------------
extern "C" void kernel_launch(void* const* d_in, const int* in_sizes, int n_in,
                              void* d_out, int out_size) {
    const float* x  = (const float*)d_in[0];
    const void*  ei = d_in[1];
    const float* W[3]     = {(const float*)d_in[2], (const float*)d_in[6],
                             (const float*)d_in[10]};
    const float* asrc[3]  = {(const float*)d_in[3], (const float*)d_in[7],
                             (const float*)d_in[11]};
    const float* adst[3]  = {(const float*)d_in[4], (const float*)d_in[8],
                             (const float*)d_in[12]};
    const float* bias[3]  = {(const float*)d_in[5], (const float*)d_in[9],
                             (const float*)d_in[13]};
    float* out = (float*)d_out;

    // one-time infra (created on the uncaptured correctness call)
    static cudaStream_t ss[NCHAIN - 1];
    static cudaEvent_t ev_fork, ev_join[NCHAIN - 1];
    static bool inited = false;
    if (!inited) {
        inited = true;
        for (int i = 0; i < NCHAIN - 1; i++) {
            cudaStreamCreateWithFlags(&ss[i], cudaStreamNonBlocking);
            cudaEventCreateWithFlags(&ev_join[i], cudaEventDisableTiming);
        }
        cudaEventCreateWithFlags(&ev_fork, cudaEventDisableTiming);
        cudaFuncSetAttribute(gemm_tc_k,
                             cudaFuncAttributeMaxDynamicSharedMemorySize,
                             GEMM_SMEM);
    }

    float *p_hw[NCHAIN], *p_x[NCHAIN], *p_w[NCHAIN], *p_as[NCHAIN], *p_ad[NCHAIN];
    {
        float4 *b_hw, *b_x, *b_w; float *b_as, *b_ad;
        cudaGetSymbolAddress((void**)&b_hw, g_hw4);
        cudaGetSymbolAddress((void**)&b_x, g_x4);
        cudaGetSymbolAddress((void**)&b_w, g_w4);
        cudaGetSymbolAddress((void**)&b_as, g_as);
        cudaGetSymbolAddress((void**)&b_ad, g_ad);
        for (int c = 0; c < NCHAIN; c++) {
            p_hw[c] = (float*)(b_hw + (size_t)c * (NN * HID / 4));
            p_x[c]  = (float*)(b_x  + (size_t)c * (NN * HID / 4));
            p_w[c]  = (float*)(b_w  + (size_t)c * EE);
            p_as[c] = b_as + (size_t)c * (NN * HEADS);
            p_ad[c] = b_ad + (size_t)c * (NN * HEADS);
        }
    }
    int *p_src, *p_dst, *p_cnt, *p_roff, *p_cur, *p_eid;
    cudaGetSymbolAddress((void**)&p_src, g_src);
    cudaGetSymbolAddress((void**)&p_dst, g_dst);
    cudaGetSymbolAddress((void**)&p_cnt, g_cnt);
    cudaGetSymbolAddress((void**)&p_roff, g_roff);
    cudaGetSymbolAddress((void**)&p_cur, g_cur);
    cudaGetSymbolAddress((void**)&p_eid, g_eid);

    // --- edge preprocessing on stream 0 ---
    detect_k<<<1, 256>>>(ei);
    convert_k<<<(EE + 255) / 256, 256>>>(ei);
    cudaMemsetAsync(p_cnt, 0, NN * sizeof(int), 0);
    hist_k<<<(EE + 255) / 256, 256>>>(p_dst, p_cnt);
    scan_k<<<1, 1024>>>(p_cnt, p_roff);
    cudaMemcpyAsync(p_cur, p_roff, NN * sizeof(int), cudaMemcpyDeviceToDevice, 0);
    scatter_k<<<(EE + 255) / 256, 256>>>(p_dst, p_cur, p_eid);

    // --- fork ---
    cudaEventRecord(ev_fork, 0);
    for (int i = 0; i < NCHAIN - 1; i++)
        cudaStreamWaitEvent(ss[i], ev_fork, 0);

    const int npblk = (NN * 32 + 255) / 256;
    const int rowblk = (NN + 127) / 128;

    for (int c = 0; c < NCHAIN; c++) {
        cudaStream_t st = (c == 0) ? (cudaStream_t)0 : ss[c - 1];
        for (int t = c; t < TT; t += NCHAIN) {
            // layer 1
            {
                dim3 gg(HID / 128, rowblk);
                gemm_tc_k<<<gg, 256, GEMM_SMEM, st>>>(
                    x + (size_t)t * IN_DIM, TT * IN_DIM, W[0], p_hw[c],
                    NN, IN_DIM, HID);
                node_prep_k<HID><<<npblk, 256, 0, st>>>(p_hw[c], asrc[0],
                                                        adst[0], p_as[c], p_ad[c]);
                gat_node_k<HID, 1><<<npblk, 256, 0, st>>>(
                    p_roff, p_eid, p_src, p_as[c], p_ad[c], p_hw[c], p_w[c],
                    bias[0], p_x[c], HID);
            }
            // layer 2
            {
                dim3 gg(HID / 128, rowblk);
                gemm_tc_k<<<gg, 256, GEMM_SMEM, st>>>(p_x[c], HID, W[1],
                                                      p_hw[c], NN, HID, HID);
                node_prep_k<HID><<<npblk, 256, 0, st>>>(p_hw[c], asrc[1],
                                                        adst[1], p_as[c], p_ad[c]);
                gat_node_k<HID, 1><<<npblk, 256, 0, st>>>(
                    p_roff, p_eid, p_src, p_as[c], p_ad[c], p_hw[c], p_w[c],
                    bias[1], p_x[c], HID);
            }
            // layer 3
            {
                dim3 gg(OUTD / 128, rowblk);
                gemm_tc_k<<<gg, 256, GEMM_SMEM, st>>>(p_x[c], HID, W[2],
                                                      p_hw[c], NN, HID, OUTD);
                node_prep_k<OUTD><<<npblk, 256, 0, st>>>(p_hw[c], asrc[2],
                                                         adst[2], p_as[c], p_ad[c]);
                gat_node_k<OUTD, 0><<<npblk, 256, 0, st>>>(
                    p_roff, p_eid, p_src, p_as[c], p_ad[c], p_hw[c], p_w[c],
                    bias[2], out + (size_t)t * OUTD, TT * OUTD);
            }
        }
    }

    // --- join ---
    for (int i = 0; i < NCHAIN - 1; i++) {
        cudaEventRecord(ev_join[i], ss[i]);
        cudaStreamWaitEvent((cudaStream_t)0, ev_join[i], 0);
    }
}